// round 10
// baseline (speedup 1.0000x reference)
#include <cuda_runtime.h>
#include <cuda_fp16.h>
#include <math.h>
#include <stdint.h>

#define N_NODES 100000
#define F_DIM   512
#define H_DIM   128
#define C_DIM   8
#define E_EDGES 1600000
#define EPSV    1e-8f

#define N_PAD   100096               // 64-row padded for GEMM tiles

#define CH      1024
#define NB      ((N_NODES + CH - 1) / CH)   // 98

// ---------------- static scratch ----------------
__device__ float g_pa[(size_t)N_NODES * C_DIM];
__device__ float g_pb[(size_t)N_NODES * C_DIM];
__device__ float g_ma[(size_t)N_NODES * C_DIM];
__device__ float g_s2[(size_t)N_NODES * C_DIM];
__device__ int   g_deg[N_NODES];
__device__ int   g_cursor[N_NODES];
__device__ int   g_rowstart[N_NODES + 1];
__device__ int   g_blocksum[NB];
__device__ int   g_blockoff[NB];
__device__ int2  g_csr[E_EDGES];                  // {src, w1bits}; w2 = w1*w1
__device__ __half g_Bt[256 * 512];                // Bt[n][k], m/s interleaved
__device__ __half g_featH[(size_t)N_PAD * F_DIM]; // feat in fp16

// ---------------- helpers ----------------
__device__ __forceinline__ uint32_t smem_u32(const void* p) {
    uint32_t a;
    asm("{ .reg .u64 t; cvta.to.shared.u64 t, %1; cvt.u32.u64 %0, t; }" : "=r"(a) : "l"(p));
    return a;
}
#define CP_ASYNC16(dst, src) \
    asm volatile("cp.async.cg.shared.global [%0], [%1], 16;" :: "r"(dst), "l"(src) : "memory")
#define CP_COMMIT()  asm volatile("cp.async.commit_group;" ::: "memory")
#define CP_WAIT0()   asm volatile("cp.async.wait_group 0;" ::: "memory")

#define MMA16816(d, a, b0v, b1v)                                                          \
    asm volatile("mma.sync.aligned.m16n8k16.row.col.f32.f16.f16.f32 "                     \
        "{%0,%1,%2,%3}, {%4,%5,%6,%7}, {%8,%9}, {%0,%1,%2,%3};"                           \
        : "+f"((d)[0]), "+f"((d)[1]), "+f"((d)[2]), "+f"((d)[3])                          \
        : "r"((a)[0]), "r"((a)[1]), "r"((a)[2]), "r"((a)[3]), "r"(b0v), "r"(b1v))

#define LDSM4(r0, r1, r2, r3, addr)                                                       \
    asm volatile("ldmatrix.sync.aligned.m8n8.x4.shared.b16 {%0,%1,%2,%3}, [%4];"          \
        : "=r"(r0), "=r"(r1), "=r"(r2), "=r"(r3) : "r"(addr))

// GEMM1 geometry: CTA = 64 rows x 256 interleaved cols, K-chunk 64, 8 chunks.
#define ASTR    72                    // fp16 elems/row (64 + 8 pad), conflict-free LDSM
#define A_ELEMS (64 * ASTR)           // 4608
#define B_ELEMS (256 * ASTR)          // 18432
#define STAGE   (A_ELEMS + B_ELEMS)   // 23040 elems
#define SMEM_GEMM (2 * STAGE * 2)     // 92160 bytes

// ---------------- prep: zero accumulators/deg + Bt fp16 ----------------
__global__ void k_prep(const float* __restrict__ Wm1, const float* __restrict__ Ws1) {
    int i = blockIdx.x * blockDim.x + threadIdx.x;
    if (i < 256 * 512) {
        int n = i >> 9, k = i & 511;
        int c = n >> 1;
        float w = (n & 1) ? Ws1[k * H_DIM + c] : Wm1[k * H_DIM + c];
        g_Bt[i] = __float2half_rn(w);
    }
    if (i < N_NODES * C_DIM) {
        g_pa[i] = 0.f;
        g_pb[i] = 0.f;
    }
    if (i < N_NODES) g_deg[i] = 0;
}

// ---------------- prep: feat fp32 -> fp16 (8 elems/thread) ----------------
__global__ void k_prepF(const float* __restrict__ feat) {
    size_t i = (size_t)blockIdx.x * blockDim.x + threadIdx.x;   // granule of 8
    const size_t tot = (size_t)N_NODES * F_DIM / 8;             // 6.4M
    if (i < tot) {
        float4 v0 = *(const float4*)&feat[i * 8];
        float4 v1 = *(const float4*)&feat[i * 8 + 4];
        __half2 h0 = make_half2(__float2half_rn(v0.x), __float2half_rn(v0.y));
        __half2 h1 = make_half2(__float2half_rn(v0.z), __float2half_rn(v0.w));
        __half2 h2 = make_half2(__float2half_rn(v1.x), __float2half_rn(v1.y));
        __half2 h3 = make_half2(__float2half_rn(v1.z), __float2half_rn(v1.w));
        uint4 o;
        o.x = *(uint32_t*)&h0; o.y = *(uint32_t*)&h1;
        o.z = *(uint32_t*)&h2; o.w = *(uint32_t*)&h3;
        *(uint4*)&g_featH[i * 8] = o;
    }
    // zero the pad rows so GEMM tiles read finite values
    const size_t padg = (size_t)(N_PAD - N_NODES) * F_DIM / 8;
    if (i < padg) {
        uint4 z = make_uint4(0, 0, 0, 0);
        *(uint4*)&g_featH[(size_t)N_NODES * F_DIM + i * 8] = z;
    }
}

// ---------------- CSR build ----------------
__global__ void k_hist(const int* __restrict__ dst) {
    int e = blockIdx.x * blockDim.x + threadIdx.x;
    if (e < E_EDGES) atomicAdd(&g_deg[dst[e]], 1);
}
__global__ void k_blocksum() {
    __shared__ int s[CH];
    int t = threadIdx.x;
    int i = blockIdx.x * CH + t;
    s[t] = (i < N_NODES) ? g_deg[i] : 0;
    __syncthreads();
    for (int d = CH / 2; d > 0; d >>= 1) {
        if (t < d) s[t] += s[t + d];
        __syncthreads();
    }
    if (t == 0) g_blocksum[blockIdx.x] = s[0];
}
__global__ void k_offscan() {
    __shared__ int s[128];
    int t = threadIdx.x;
    int v = (t < NB) ? g_blocksum[t] : 0;
    s[t] = v;
    __syncthreads();
    for (int d = 1; d < 128; d <<= 1) {
        int x = (t >= d) ? s[t - d] : 0;
        __syncthreads();
        s[t] += x;
        __syncthreads();
    }
    if (t < NB) g_blockoff[t] = s[t] - v;
}
__global__ void k_scan_chunk() {
    __shared__ int s[CH];
    int t = threadIdx.x;
    int b = blockIdx.x;
    int i = b * CH + t;
    int v = (i < N_NODES) ? g_deg[i] : 0;
    s[t] = v;
    __syncthreads();
    for (int d = 1; d < CH; d <<= 1) {
        int x = (t >= d) ? s[t - d] : 0;
        __syncthreads();
        s[t] += x;
        __syncthreads();
    }
    int excl = g_blockoff[b] + s[t] - v;
    if (i < N_NODES) {
        g_rowstart[i] = excl;
        g_cursor[i]   = excl;
    }
    if (i == N_NODES - 1) g_rowstart[N_NODES] = excl + v;
}
__global__ void k_scatter(const int* __restrict__ src, const int* __restrict__ dst,
                          const float* __restrict__ w1) {
    int e = blockIdx.x * blockDim.x + threadIdx.x;
    if (e < E_EDGES) {
        int d = dst[e];
        int pos = atomicAdd(&g_cursor[d], 1);
        g_csr[pos] = make_int2(src[e], __float_as_int(w1[e]));
    }
}

// ---------------- GEMM1: all-cp.async 64x256, K-chunk 64, fused proj epilogue ----
__global__ __launch_bounds__(256, 2)
void k_gemm1_mma(const float* __restrict__ Wm2, const float* __restrict__ Ws2) {
    extern __shared__ __half sm[];
    __shared__ float wm2s[H_DIM * C_DIM];
    __shared__ float ws2s[H_DIM * C_DIM];
    const int tid  = threadIdx.x;
    const int lane = tid & 31;
    const int wid  = tid >> 5;
    const int wm   = wid & 1;          // 2 row-warps (32 rows each)
    const int wn   = wid >> 1;         // 4 col-warps (64 interleaved cols each)
    const int rowbase = blockIdx.x * 64;
    const int la      = lane & 3;

    for (int i = tid; i < H_DIM * C_DIM; i += 256) {
        wm2s[i] = Wm2[i];
        ws2s[i] = Ws2[i];
    }

    const int a_lrow = (lane & 7) + ((lane >> 3) & 1) * 8;
    const int a_koff = (lane >> 4) * 16;
    const int b_lrow = (lane & 7);
    const int b_nsel = (lane >> 4);
    const int b_koff = ((lane >> 3) & 1) * 16;

    // A copy: 2 granules per thread (512 total), fixed (row, seg)
    const int arow0 = tid >> 3;               // 0..31
    const int aseg0 = tid & 7;
    const int arow1 = (tid + 256) >> 3;       // 32..63
    const int aseg1 = aseg0;
    const __half* aS0 = &g_featH[(size_t)(rowbase + arow0) * F_DIM + aseg0 * 8];
    const __half* aS1 = &g_featH[(size_t)(rowbase + arow1) * F_DIM + aseg1 * 8];
    const uint32_t smbase = smem_u32(sm);
    const uint32_t aD0 = (uint32_t)(arow0 * ASTR + aseg0 * 8) * 2;
    const uint32_t aD1 = (uint32_t)(arow1 * ASTR + aseg1 * 8) * 2;

    float acc[2][8][4];
#pragma unroll
    for (int mi = 0; mi < 2; mi++)
#pragma unroll
        for (int ni = 0; ni < 8; ni++)
#pragma unroll
            for (int q = 0; q < 4; q++) acc[mi][ni][q] = 0.f;

    // ---- prologue: stage 0 ----
    CP_ASYNC16(smbase + aD0, aS0);
    CP_ASYNC16(smbase + aD1, aS1);
#pragma unroll
    for (int j = 0; j < 8; j++) {
        int idx = tid + (j << 8);
        int n   = idx >> 3;
        int seg = idx & 7;
        uint32_t d = smbase + (uint32_t)(A_ELEMS + n * ASTR + seg * 8) * 2;
        CP_ASYNC16(d, &g_Bt[(size_t)n * 512 + seg * 8]);
    }
    CP_COMMIT();
    CP_WAIT0();
    __syncthreads();

#pragma unroll 1
    for (int chunk = 0; chunk < 8; chunk++) {
        const uint32_t stoff  = (chunk & 1) ? (uint32_t)STAGE * 2 : 0u;
        const uint32_t stnoff = (chunk & 1) ? 0u : (uint32_t)STAGE * 2;

        if (chunk < 7) {
            const int k0 = (chunk + 1) << 6;
            CP_ASYNC16(smbase + stnoff + aD0, aS0 + k0);
            CP_ASYNC16(smbase + stnoff + aD1, aS1 + k0);
#pragma unroll
            for (int j = 0; j < 8; j++) {
                int idx = tid + (j << 8);
                int n   = idx >> 3;
                int seg = idx & 7;
                uint32_t d = smbase + stnoff + (uint32_t)(A_ELEMS + n * ASTR + seg * 8) * 2;
                CP_ASYNC16(d, &g_Bt[(size_t)n * 512 + k0 + seg * 8]);
            }
            CP_COMMIT();
        }

        const uint32_t sA = smbase + stoff;
        const uint32_t sB = sA + A_ELEMS * 2;
#pragma unroll
        for (int ks = 0; ks < 4; ks++) {
            const uint32_t kbyte = ks * 32;
            uint32_t ahf[2][4];
#pragma unroll
            for (int mi = 0; mi < 2; mi++) {
                uint32_t ro = (uint32_t)(wm * 32 + mi * 16 + a_lrow) * (ASTR * 2) + kbyte + a_koff;
                LDSM4(ahf[mi][0], ahf[mi][1], ahf[mi][2], ahf[mi][3], sA + ro);
            }
#pragma unroll
            for (int nip = 0; nip < 4; nip++) {
                uint32_t bo = (uint32_t)(wn * 64 + (nip * 2 + b_nsel) * 8 + b_lrow) * (ASTR * 2)
                              + kbyte + b_koff;
                uint32_t b0, b1, b2, b3;
                LDSM4(b0, b1, b2, b3, sB + bo);
#pragma unroll
                for (int mi = 0; mi < 2; mi++) {
                    MMA16816(acc[mi][2 * nip],     ahf[mi], b0, b1);
                    MMA16816(acc[mi][2 * nip + 1], ahf[mi], b2, b3);
                }
            }
        }

        if (chunk < 7) CP_WAIT0();
        __syncthreads();
    }

    // ---- epilogue: activations + fused 128->8 projection + atomic reduce ----
    const int chbase = wn * 32;
#pragma unroll
    for (int mi = 0; mi < 2; mi++) {
#pragma unroll
        for (int half8 = 0; half8 < 2; half8++) {
            int row = rowbase + wm * 32 + mi * 16 + half8 * 8 + (lane >> 2);
            float pa[8], pb[8];
#pragma unroll
            for (int c = 0; c < 8; c++) { pa[c] = 0.f; pb[c] = 0.f; }
#pragma unroll
            for (int ni = 0; ni < 8; ni++) {
                float m  = acc[mi][ni][half8 * 2 + 0];
                float s  = acc[mi][ni][half8 * 2 + 1];
                float sr = fmaxf(s, 0.f);
                float a1 = __expf(-sr);
                float e  = (m > 0.f) ? m : expm1f(m);
                float xa = e * a1;
                float xb = sr * a1 * a1;
                int ch = chbase + ni * 4 + la;
#pragma unroll
                for (int c = 0; c < 8; c++) {
                    pa[c] = fmaf(xa, wm2s[ch * 8 + c], pa[c]);
                    pb[c] = fmaf(xb, ws2s[ch * 8 + c], pb[c]);
                }
            }
#pragma unroll
            for (int o = 1; o <= 2; o <<= 1) {
#pragma unroll
                for (int c = 0; c < 8; c++) {
                    pa[c] += __shfl_xor_sync(0xffffffffu, pa[c], o);
                    pb[c] += __shfl_xor_sync(0xffffffffu, pb[c], o);
                }
            }
            if (row < N_NODES) {
                int c0 = la * 2;
                atomicAdd(&g_pa[(size_t)row * C_DIM + c0],     pa[c0]);
                atomicAdd(&g_pa[(size_t)row * C_DIM + c0 + 1], pa[c0 + 1]);
                atomicAdd(&g_pb[(size_t)row * C_DIM + c0],     pb[c0]);
                atomicAdd(&g_pb[(size_t)row * C_DIM + c0 + 1], pb[c0 + 1]);
            }
        }
    }
}

// ---------------- agg in 8-dim + layer-2 activations ----------------
__global__ __launch_bounds__(256)
void k_agg1p() {
    int n    = (blockIdx.x * blockDim.x + threadIdx.x) >> 5;
    int lane = threadIdx.x & 31;
    if (n >= N_NODES) return;
    int s = g_rowstart[n];
    int e = g_rowstart[n + 1];
    int c = lane & 7;
    int g = lane >> 3;
    float a1 = 0.f, a2 = 0.f;
    for (int j = s + g; j < e; j += 4) {
        int2 e2 = g_csr[j];
        float w1 = __int_as_float(e2.y);
        float w2 = w1 * w1;
        a1 = fmaf(w1, g_pa[(size_t)e2.x * C_DIM + c], a1);
        a2 = fmaf(w2, g_pb[(size_t)e2.x * C_DIM + c], a2);
    }
    a1 += __shfl_down_sync(0xffffffffu, a1, 16);
    a2 += __shfl_down_sync(0xffffffffu, a2, 16);
    a1 += __shfl_down_sync(0xffffffffu, a1, 8);
    a2 += __shfl_down_sync(0xffffffffu, a2, 8);
    if (lane < 8) {
        float s2   = fmaxf(a2, 0.f);
        float miu2 = (a1 > 0.f) ? a1 : expm1f(a1);
        g_ma[(size_t)n * C_DIM + lane] = miu2 * __expf(-s2);
        g_s2[(size_t)n * C_DIM + lane] = s2;
    }
}

// ---------------- Aggregation 2 + reparameterized sample ----------------
__global__ __launch_bounds__(256)
void k_agg2(const float* __restrict__ noise, float* __restrict__ out) {
    int n    = (blockIdx.x * blockDim.x + threadIdx.x) >> 5;
    int lane = threadIdx.x & 31;
    if (n >= N_NODES) return;
    int s = g_rowstart[n];
    int e = g_rowstart[n + 1];
    int c = lane & 7;
    int g = lane >> 3;
    float acc = 0.f;
    for (int j = s + g; j < e; j += 4) {
        int2 e2 = g_csr[j];
        float w = __int_as_float(e2.y);
        acc = fmaf(w, g_ma[(size_t)e2.x * C_DIM + c], acc);
    }
    acc += __shfl_down_sync(0xffffffffu, acc, 16);
    acc += __shfl_down_sync(0xffffffffu, acc, 8);
    if (lane < 8) {
        size_t o = (size_t)n * C_DIM + c;
        float s2 = g_s2[o];
        out[o] = acc + noise[o] * sqrtf(s2 + EPSV);
    }
}

// ---------------- launch ----------------
extern "C" void kernel_launch(void* const* d_in, const int* in_sizes, int n_in,
                              void* d_out, int out_size) {
    (void)in_sizes; (void)n_in; (void)out_size;
    const float* feat  = (const float*)d_in[0];
    const int*   esrc  = (const int*)d_in[1];
    const int*   edst  = (const int*)d_in[2];
    const float* w1    = (const float*)d_in[3];
    const float* Wm1   = (const float*)d_in[5];
    const float* Ws1   = (const float*)d_in[6];
    const float* Wm2   = (const float*)d_in[7];
    const float* Ws2   = (const float*)d_in[8];
    const float* noise = (const float*)d_in[9];
    float*       out   = (float*)d_out;

    cudaFuncSetAttribute(k_gemm1_mma, cudaFuncAttributeMaxDynamicSharedMemorySize,
                         SMEM_GEMM);

    k_prep<<<(N_NODES * C_DIM + CH - 1) / CH, CH>>>(Wm1, Ws1);     // 0
    k_prepF<<<(int)(((size_t)N_NODES * F_DIM / 8 + 255) / 256), 256>>>(feat); // 1
    k_hist<<<(E_EDGES + 255) / 256, 256>>>(edst);                  // 2
    k_gemm1_mma<<<(N_NODES + 63) / 64, 256, SMEM_GEMM>>>(Wm2, Ws2); // 3 <- ncu
    k_blocksum<<<NB, CH>>>();                                      // 4
    k_offscan<<<1, 128>>>();                                       // 5
    k_scan_chunk<<<NB, CH>>>();                                    // 6
    k_scatter<<<(E_EDGES + 255) / 256, 256>>>(esrc, edst, w1);     // 7
    k_agg1p<<<(N_NODES + 7) / 8, 256>>>();                         // 8
    k_agg2<<<(N_NODES + 7) / 8, 256>>>(noise, out);                // 9
}

// round 11
// speedup vs baseline: 1.1111x; 1.1111x over previous
#include <cuda_runtime.h>
#include <cuda_fp16.h>
#include <math.h>
#include <stdint.h>

#define N_NODES 100000
#define F_DIM   512
#define H_DIM   128
#define C_DIM   8
#define E_EDGES 1600000
#define EPSV    1e-8f

#define CH      1024
#define NB      ((N_NODES + CH - 1) / CH)   // 98

// ---------------- static scratch ----------------
__device__ float g_pa[(size_t)N_NODES * C_DIM];
__device__ float g_pb[(size_t)N_NODES * C_DIM];
__device__ float g_ma[(size_t)N_NODES * C_DIM];
__device__ float g_s2[(size_t)N_NODES * C_DIM];
__device__ int   g_deg[N_NODES];
__device__ int   g_cursor[N_NODES];
__device__ int   g_rowstart[N_NODES + 1];
__device__ int   g_blocksum[NB];
__device__ int   g_blockoff[NB];
__device__ int2  g_csr[E_EDGES];                  // {src, w1bits}; w2 = w1*w1
__device__ __half g_Bt[256 * 512];                // Bt[n][k], m/s interleaved

// ---------------- helpers ----------------
__device__ __forceinline__ uint32_t smem_u32(const void* p) {
    uint32_t a;
    asm("{ .reg .u64 t; cvta.to.shared.u64 t, %1; cvt.u32.u64 %0, t; }" : "=r"(a) : "l"(p));
    return a;
}
#define CP_ASYNC16(dst, src) \
    asm volatile("cp.async.cg.shared.global [%0], [%1], 16;" :: "r"(dst), "l"(src) : "memory")
#define CP_COMMIT()  asm volatile("cp.async.commit_group;" ::: "memory")
#define CP_WAIT0()   asm volatile("cp.async.wait_group 0;" ::: "memory")

#define MMA16816(d, a, b0v, b1v)                                                          \
    asm volatile("mma.sync.aligned.m16n8k16.row.col.f32.f16.f16.f32 "                     \
        "{%0,%1,%2,%3}, {%4,%5,%6,%7}, {%8,%9}, {%0,%1,%2,%3};"                           \
        : "+f"((d)[0]), "+f"((d)[1]), "+f"((d)[2]), "+f"((d)[3])                          \
        : "r"((a)[0]), "r"((a)[1]), "r"((a)[2]), "r"((a)[3]), "r"(b0v), "r"(b1v))

#define LDSM4(r0, r1, r2, r3, addr)                                                       \
    asm volatile("ldmatrix.sync.aligned.m8n8.x4.shared.b16 {%0,%1,%2,%3}, [%4];"          \
        : "=r"(r0), "=r"(r1), "=r"(r2), "=r"(r3) : "r"(addr))

// GEMM1 geometry: CTA = 64 rows x 256 interleaved cols, K-chunk 64, 8 chunks.
#define ASTR    72                    // fp16 elems/row (64 + 8 pad), conflict-free LDSM
#define A_ELEMS (64 * ASTR)           // 4608
#define B_ELEMS (256 * ASTR)          // 18432
#define STAGE   (A_ELEMS + B_ELEMS)   // 23040 elems
#define SMEM_GEMM (2 * STAGE * 2)     // 92160 bytes

// ---------------- prep: zero accumulators/deg + Bt fp16 ----------------
__global__ void k_prep(const float* __restrict__ Wm1, const float* __restrict__ Ws1) {
    int i = blockIdx.x * blockDim.x + threadIdx.x;
    if (i < 256 * 512) {
        int n = i >> 9, k = i & 511;
        int c = n >> 1;
        float w = (n & 1) ? Ws1[k * H_DIM + c] : Wm1[k * H_DIM + c];
        g_Bt[i] = __float2half_rn(w);
    }
    if (i < N_NODES * C_DIM) {
        g_pa[i] = 0.f;
        g_pb[i] = 0.f;
    }
    if (i < N_NODES) g_deg[i] = 0;
}

// ---------------- CSR build ----------------
__global__ void k_hist(const int* __restrict__ dst) {
    int e = blockIdx.x * blockDim.x + threadIdx.x;
    if (e < E_EDGES) atomicAdd(&g_deg[dst[e]], 1);
}
__global__ void k_blocksum() {
    __shared__ int s[CH];
    int t = threadIdx.x;
    int i = blockIdx.x * CH + t;
    s[t] = (i < N_NODES) ? g_deg[i] : 0;
    __syncthreads();
    for (int d = CH / 2; d > 0; d >>= 1) {
        if (t < d) s[t] += s[t + d];
        __syncthreads();
    }
    if (t == 0) g_blocksum[blockIdx.x] = s[0];
}
__global__ void k_offscan() {
    __shared__ int s[128];
    int t = threadIdx.x;
    int v = (t < NB) ? g_blocksum[t] : 0;
    s[t] = v;
    __syncthreads();
    for (int d = 1; d < 128; d <<= 1) {
        int x = (t >= d) ? s[t - d] : 0;
        __syncthreads();
        s[t] += x;
        __syncthreads();
    }
    if (t < NB) g_blockoff[t] = s[t] - v;
}
__global__ void k_scan_chunk() {
    __shared__ int s[CH];
    int t = threadIdx.x;
    int b = blockIdx.x;
    int i = b * CH + t;
    int v = (i < N_NODES) ? g_deg[i] : 0;
    s[t] = v;
    __syncthreads();
    for (int d = 1; d < CH; d <<= 1) {
        int x = (t >= d) ? s[t - d] : 0;
        __syncthreads();
        s[t] += x;
        __syncthreads();
    }
    int excl = g_blockoff[b] + s[t] - v;
    if (i < N_NODES) {
        g_rowstart[i] = excl;
        g_cursor[i]   = excl;
    }
    if (i == N_NODES - 1) g_rowstart[N_NODES] = excl + v;
}
__global__ void k_scatter(const int* __restrict__ src, const int* __restrict__ dst,
                          const float* __restrict__ w1) {
    int e = blockIdx.x * blockDim.x + threadIdx.x;
    if (e < E_EDGES) {
        int d = dst[e];
        int pos = atomicAdd(&g_cursor[d], 1);
        g_csr[pos] = make_int2(src[e], __float_as_int(w1[e]));
    }
}

// ---------------- GEMM1: 64x256, K-chunk 64, cp.async B + fused proj epilogue ----
__device__ __forceinline__ void store_A_stage(__half* st, const float4* av, int tid) {
#pragma unroll
    for (int j = 0; j < 4; j++) {
        int idx = tid + (j << 8);          // 0..1023
        int r   = idx >> 4;                // 0..63
        int c4  = (idx & 15) << 2;         // 0..60
        float4 v = av[j];
        __half h0 = __float2half_rn(v.x);
        __half h1 = __float2half_rn(v.y);
        __half h2 = __float2half_rn(v.z);
        __half h3 = __float2half_rn(v.w);
        uint32_t hp0 = ((uint32_t)*(uint16_t*)&h1 << 16) | *(uint16_t*)&h0;
        uint32_t hp1 = ((uint32_t)*(uint16_t*)&h3 << 16) | *(uint16_t*)&h2;
        *(uint2*)&st[r * ASTR + c4] = make_uint2(hp0, hp1);
    }
}

__global__ __launch_bounds__(256, 2)
void k_gemm1_mma(const float* __restrict__ feat,
                 const float* __restrict__ Wm2, const float* __restrict__ Ws2) {
    extern __shared__ __half sm[];
    __shared__ float wm2s[H_DIM * C_DIM];
    __shared__ float ws2s[H_DIM * C_DIM];
    const int tid  = threadIdx.x;
    const int lane = tid & 31;
    const int wid  = tid >> 5;
    const int wm   = wid & 1;          // 2 row-warps (32 rows each)
    const int wn   = wid >> 1;         // 4 col-warps (64 interleaved cols each)
    const int rowbase = blockIdx.x * 64;
    const int la      = lane & 3;

    for (int i = tid; i < H_DIM * C_DIM; i += 256) {
        wm2s[i] = Wm2[i];
        ws2s[i] = Ws2[i];
    }

    const int a_lrow = (lane & 7) + ((lane >> 3) & 1) * 8;
    const int a_koff = (lane >> 4) * 16;
    const int b_lrow = (lane & 7);
    const int b_nsel = (lane >> 4);
    const int b_koff = ((lane >> 3) & 1) * 16;

    float acc[2][8][4];
#pragma unroll
    for (int mi = 0; mi < 2; mi++)
#pragma unroll
        for (int ni = 0; ni < 8; ni++)
#pragma unroll
            for (int q = 0; q < 4; q++) acc[mi][ni][q] = 0.f;

    float4 av[4];
    // ---- prologue: chunk 0 ----
#pragma unroll
    for (int j = 0; j < 4; j++) {
        int idx = tid + (j << 8);
        int r   = idx >> 4;
        int c4  = (idx & 15) << 2;
        int grow = rowbase + r;
        if (grow >= N_NODES) grow = N_NODES - 1;
        av[j] = *(const float4*)&feat[(size_t)grow * F_DIM + c4];
    }
#pragma unroll
    for (int j = 0; j < 8; j++) {
        int idx = tid + (j << 8);          // 0..2047
        int n   = idx >> 3;                // 0..255
        int seg = idx & 7;                 // 0..7 (16B granules of 128B row)
        uint32_t d = smem_u32(&sm[A_ELEMS + n * ASTR + seg * 8]);
        CP_ASYNC16(d, &g_Bt[(size_t)n * 512 + seg * 8]);
    }
    CP_COMMIT();
    store_A_stage(sm, av, tid);
    CP_WAIT0();
    __syncthreads();

#pragma unroll 1
    for (int chunk = 0; chunk < 8; chunk++) {
        __half* st  = sm + (chunk & 1) * STAGE;
        __half* stn = sm + ((chunk & 1) ^ 1) * STAGE;

        if (chunk < 7) {
            const int k0 = (chunk + 1) << 6;
#pragma unroll
            for (int j = 0; j < 4; j++) {
                int idx = tid + (j << 8);
                int r   = idx >> 4;
                int c4  = (idx & 15) << 2;
                int grow = rowbase + r;
                if (grow >= N_NODES) grow = N_NODES - 1;
                av[j] = *(const float4*)&feat[(size_t)grow * F_DIM + k0 + c4];
            }
#pragma unroll
            for (int j = 0; j < 8; j++) {
                int idx = tid + (j << 8);
                int n   = idx >> 3;
                int seg = idx & 7;
                uint32_t d = smem_u32(&stn[A_ELEMS + n * ASTR + seg * 8]);
                CP_ASYNC16(d, &g_Bt[(size_t)n * 512 + k0 + seg * 8]);
            }
            CP_COMMIT();
        }

        const uint32_t sA = smem_u32(st);
        const uint32_t sB = sA + A_ELEMS * 2;
#pragma unroll
        for (int ks = 0; ks < 4; ks++) {
            const uint32_t kbyte = ks * 32;
            uint32_t ahf[2][4];
#pragma unroll
            for (int mi = 0; mi < 2; mi++) {
                uint32_t ro = (uint32_t)(wm * 32 + mi * 16 + a_lrow) * (ASTR * 2) + kbyte + a_koff;
                LDSM4(ahf[mi][0], ahf[mi][1], ahf[mi][2], ahf[mi][3], sA + ro);
            }
#pragma unroll
            for (int nip = 0; nip < 4; nip++) {
                uint32_t bo = (uint32_t)(wn * 64 + (nip * 2 + b_nsel) * 8 + b_lrow) * (ASTR * 2)
                              + kbyte + b_koff;
                uint32_t b0, b1, b2, b3;
                LDSM4(b0, b1, b2, b3, sB + bo);
#pragma unroll
                for (int mi = 0; mi < 2; mi++) {
                    MMA16816(acc[mi][2 * nip],     ahf[mi], b0, b1);
                    MMA16816(acc[mi][2 * nip + 1], ahf[mi], b2, b3);
                }
            }
        }

        if (chunk < 7) {
            store_A_stage(stn, av, tid);
            CP_WAIT0();
        }
        __syncthreads();
    }

    // ---- epilogue: activations + fused 128->8 projection + atomic reduce ----
    const int chbase = wn * 32;
#pragma unroll
    for (int mi = 0; mi < 2; mi++) {
#pragma unroll
        for (int half8 = 0; half8 < 2; half8++) {
            int row = rowbase + wm * 32 + mi * 16 + half8 * 8 + (lane >> 2);
            float pa[8], pb[8];
#pragma unroll
            for (int c = 0; c < 8; c++) { pa[c] = 0.f; pb[c] = 0.f; }
#pragma unroll
            for (int ni = 0; ni < 8; ni++) {
                float m  = acc[mi][ni][half8 * 2 + 0];
                float s  = acc[mi][ni][half8 * 2 + 1];
                float sr = fmaxf(s, 0.f);
                float a1 = __expf(-sr);
                float e  = (m > 0.f) ? m : expm1f(m);
                float xa = e * a1;
                float xb = sr * a1 * a1;
                int ch = chbase + ni * 4 + la;
#pragma unroll
                for (int c = 0; c < 8; c++) {
                    pa[c] = fmaf(xa, wm2s[ch * 8 + c], pa[c]);
                    pb[c] = fmaf(xb, ws2s[ch * 8 + c], pb[c]);
                }
            }
#pragma unroll
            for (int o = 1; o <= 2; o <<= 1) {
#pragma unroll
                for (int c = 0; c < 8; c++) {
                    pa[c] += __shfl_xor_sync(0xffffffffu, pa[c], o);
                    pb[c] += __shfl_xor_sync(0xffffffffu, pb[c], o);
                }
            }
            if (row < N_NODES) {
                int c0 = la * 2;
                atomicAdd(&g_pa[(size_t)row * C_DIM + c0],     pa[c0]);
                atomicAdd(&g_pa[(size_t)row * C_DIM + c0 + 1], pa[c0 + 1]);
                atomicAdd(&g_pb[(size_t)row * C_DIM + c0],     pb[c0]);
                atomicAdd(&g_pb[(size_t)row * C_DIM + c0 + 1], pb[c0 + 1]);
            }
        }
    }
}

// ---------------- agg in 8-dim + layer-2 activations ----------------
__global__ __launch_bounds__(256)
void k_agg1p() {
    int n    = (blockIdx.x * blockDim.x + threadIdx.x) >> 5;
    int lane = threadIdx.x & 31;
    if (n >= N_NODES) return;
    int s = g_rowstart[n];
    int e = g_rowstart[n + 1];
    int c = lane & 7;
    int g = lane >> 3;
    float a1 = 0.f, a2 = 0.f;
    for (int j = s + g; j < e; j += 4) {
        int2 e2 = g_csr[j];
        float w1 = __int_as_float(e2.y);
        float w2 = w1 * w1;
        a1 = fmaf(w1, g_pa[(size_t)e2.x * C_DIM + c], a1);
        a2 = fmaf(w2, g_pb[(size_t)e2.x * C_DIM + c], a2);
    }
    a1 += __shfl_down_sync(0xffffffffu, a1, 16);
    a2 += __shfl_down_sync(0xffffffffu, a2, 16);
    a1 += __shfl_down_sync(0xffffffffu, a1, 8);
    a2 += __shfl_down_sync(0xffffffffu, a2, 8);
    if (lane < 8) {
        float s2   = fmaxf(a2, 0.f);
        float miu2 = (a1 > 0.f) ? a1 : expm1f(a1);
        g_ma[(size_t)n * C_DIM + lane] = miu2 * __expf(-s2);
        g_s2[(size_t)n * C_DIM + lane] = s2;
    }
}

// ---------------- Aggregation 2 + reparameterized sample ----------------
__global__ __launch_bounds__(256)
void k_agg2(const float* __restrict__ noise, float* __restrict__ out) {
    int n    = (blockIdx.x * blockDim.x + threadIdx.x) >> 5;
    int lane = threadIdx.x & 31;
    if (n >= N_NODES) return;
    int s = g_rowstart[n];
    int e = g_rowstart[n + 1];
    int c = lane & 7;
    int g = lane >> 3;
    float acc = 0.f;
    for (int j = s + g; j < e; j += 4) {
        int2 e2 = g_csr[j];
        float w = __int_as_float(e2.y);
        acc = fmaf(w, g_ma[(size_t)e2.x * C_DIM + c], acc);
    }
    acc += __shfl_down_sync(0xffffffffu, acc, 16);
    acc += __shfl_down_sync(0xffffffffu, acc, 8);
    if (lane < 8) {
        size_t o = (size_t)n * C_DIM + c;
        float s2 = g_s2[o];
        out[o] = acc + noise[o] * sqrtf(s2 + EPSV);
    }
}

// ---------------- launch: fork CSR chain onto a side stream under the GEMM ----
extern "C" void kernel_launch(void* const* d_in, const int* in_sizes, int n_in,
                              void* d_out, int out_size) {
    (void)in_sizes; (void)n_in; (void)out_size;
    const float* feat  = (const float*)d_in[0];
    const int*   esrc  = (const int*)d_in[1];
    const int*   edst  = (const int*)d_in[2];
    const float* w1    = (const float*)d_in[3];
    const float* Wm1   = (const float*)d_in[5];
    const float* Ws1   = (const float*)d_in[6];
    const float* Wm2   = (const float*)d_in[7];
    const float* Ws2   = (const float*)d_in[8];
    const float* noise = (const float*)d_in[9];
    float*       out   = (float*)d_out;

    static cudaStream_t s2 = nullptr;
    static cudaEvent_t  evF = nullptr, evJ = nullptr;
    static bool         inited = false;
    if (!inited) {
        cudaFuncSetAttribute(k_gemm1_mma, cudaFuncAttributeMaxDynamicSharedMemorySize,
                             SMEM_GEMM);
        cudaStreamCreateWithFlags(&s2, cudaStreamNonBlocking);
        cudaEventCreateWithFlags(&evF, cudaEventDisableTiming);
        cudaEventCreateWithFlags(&evJ, cudaEventDisableTiming);
        inited = true;
    }

    // main: prep (zeros deg/pa/pb + Bt) -- both chains depend on it
    k_prep<<<(N_NODES * C_DIM + CH - 1) / CH, CH>>>(Wm1, Ws1);

    // fork
    cudaEventRecord(evF, 0);
    cudaStreamWaitEvent(s2, evF, 0);

    // side stream: CSR build chain (independent of GEMM)
    k_hist<<<(E_EDGES + 255) / 256, 256, 0, s2>>>(edst);
    k_blocksum<<<NB, CH, 0, s2>>>();
    k_offscan<<<1, 128, 0, s2>>>();
    k_scan_chunk<<<NB, CH, 0, s2>>>();
    k_scatter<<<(E_EDGES + 255) / 256, 256, 0, s2>>>(esrc, edst, w1);

    // main: the big GEMM (hides the CSR chain)
    k_gemm1_mma<<<(N_NODES + 63) / 64, 256, SMEM_GEMM>>>(feat, Wm2, Ws2);

    // join
    cudaEventRecord(evJ, s2);
    cudaStreamWaitEvent(0, evJ, 0);

    // main: aggregations (need both CSR and GEMM results)
    k_agg1p<<<(N_NODES + 7) / 8, 256>>>();
    k_agg2<<<(N_NODES + 7) / 8, 256>>>(noise, out);
}

// round 13
// speedup vs baseline: 1.2088x; 1.0880x over previous
#include <cuda_runtime.h>
#include <cuda_fp16.h>
#include <math.h>
#include <stdint.h>

#define N_NODES 100000
#define F_DIM   512
#define H_DIM   128
#define C_DIM   8
#define E_EDGES 1600000
#define EPSV    1e-8f

#define CH      1024
#define NB      ((N_NODES + CH - 1) / CH)   // 98

// ---------------- static scratch ----------------
__device__ float g_pa[(size_t)N_NODES * C_DIM];
__device__ float g_pb[(size_t)N_NODES * C_DIM];
__device__ float g_ma[(size_t)N_NODES * C_DIM];
__device__ float g_s2[(size_t)N_NODES * C_DIM];
__device__ int   g_deg[N_NODES];
__device__ int   g_cursor[N_NODES];
__device__ int   g_rowstart[N_NODES + 1];
__device__ int   g_blocksum[NB];
__device__ int   g_blockoff[NB];
__device__ int2  g_csr[E_EDGES];                  // {src, w1bits}; w2 = w1*w1
__device__ __half g_Bt[256 * 512];                // Bt[n][k], m/s interleaved

// ---------------- helpers ----------------
__device__ __forceinline__ uint32_t smem_u32(const void* p) {
    uint32_t a;
    asm("{ .reg .u64 t; cvta.to.shared.u64 t, %1; cvt.u32.u64 %0, t; }" : "=r"(a) : "l"(p));
    return a;
}
#define CP_ASYNC16(dst, src) \
    asm volatile("cp.async.cg.shared.global [%0], [%1], 16;" :: "r"(dst), "l"(src) : "memory")
#define CP_COMMIT()  asm volatile("cp.async.commit_group;" ::: "memory")
#define CP_WAIT0()   asm volatile("cp.async.wait_group 0;" ::: "memory")

#define MMA16816(d, a, b0v, b1v)                                                          \
    asm volatile("mma.sync.aligned.m16n8k16.row.col.f32.f16.f16.f32 "                     \
        "{%0,%1,%2,%3}, {%4,%5,%6,%7}, {%8,%9}, {%0,%1,%2,%3};"                           \
        : "+f"((d)[0]), "+f"((d)[1]), "+f"((d)[2]), "+f"((d)[3])                          \
        : "r"((a)[0]), "r"((a)[1]), "r"((a)[2]), "r"((a)[3]), "r"(b0v), "r"(b1v))

#define LDSM4(r0, r1, r2, r3, addr)                                                       \
    asm volatile("ldmatrix.sync.aligned.m8n8.x4.shared.b16 {%0,%1,%2,%3}, [%4];"          \
        : "=r"(r0), "=r"(r1), "=r"(r2), "=r"(r3) : "r"(addr))

// GEMM1 geometry: CTA = 64 rows x 128 interleaved cols, K-chunk 64, 8 chunks.
#define ASTR    72                    // fp16 elems/row (64 + 8 pad), conflict-free LDSM
#define A_ELEMS (64 * ASTR)           // 4608
#define B_ELEMS (128 * ASTR)          // 9216
#define STAGE   (A_ELEMS + B_ELEMS)   // 13824 elems
#define SMEM_GEMM (2 * STAGE * 2)     // 55296 bytes

// ---------------- prep: zero accumulators/deg + Bt fp16 ----------------
__global__ void k_prep(const float* __restrict__ Wm1, const float* __restrict__ Ws1) {
    int i = blockIdx.x * blockDim.x + threadIdx.x;
    if (i < 256 * 512) {
        int n = i >> 9, k = i & 511;
        int c = n >> 1;
        float w = (n & 1) ? Ws1[k * H_DIM + c] : Wm1[k * H_DIM + c];
        g_Bt[i] = __float2half_rn(w);
    }
    if (i < N_NODES * C_DIM) {
        g_pa[i] = 0.f;
        g_pb[i] = 0.f;
    }
    if (i < N_NODES) g_deg[i] = 0;
}

// ---------------- CSR build ----------------
__global__ void k_hist(const int* __restrict__ dst) {
    int e = blockIdx.x * blockDim.x + threadIdx.x;
    if (e < E_EDGES) atomicAdd(&g_deg[dst[e]], 1);
}
__global__ void k_blocksum() {
    __shared__ int s[CH];
    int t = threadIdx.x;
    int i = blockIdx.x * CH + t;
    s[t] = (i < N_NODES) ? g_deg[i] : 0;
    __syncthreads();
    for (int d = CH / 2; d > 0; d >>= 1) {
        if (t < d) s[t] += s[t + d];
        __syncthreads();
    }
    if (t == 0) g_blocksum[blockIdx.x] = s[0];
}
__global__ void k_offscan() {
    __shared__ int s[128];
    int t = threadIdx.x;
    int v = (t < NB) ? g_blocksum[t] : 0;
    s[t] = v;
    __syncthreads();
    for (int d = 1; d < 128; d <<= 1) {
        int x = (t >= d) ? s[t - d] : 0;
        __syncthreads();
        s[t] += x;
        __syncthreads();
    }
    if (t < NB) g_blockoff[t] = s[t] - v;
}
__global__ void k_scan_chunk() {
    __shared__ int s[CH];
    int t = threadIdx.x;
    int b = blockIdx.x;
    int i = b * CH + t;
    int v = (i < N_NODES) ? g_deg[i] : 0;
    s[t] = v;
    __syncthreads();
    for (int d = 1; d < CH; d <<= 1) {
        int x = (t >= d) ? s[t - d] : 0;
        __syncthreads();
        s[t] += x;
        __syncthreads();
    }
    int excl = g_blockoff[b] + s[t] - v;
    if (i < N_NODES) {
        g_rowstart[i] = excl;
        g_cursor[i]   = excl;
    }
    if (i == N_NODES - 1) g_rowstart[N_NODES] = excl + v;
}
__global__ void k_scatter(const int* __restrict__ src, const int* __restrict__ dst,
                          const float* __restrict__ w1) {
    int e = blockIdx.x * blockDim.x + threadIdx.x;
    if (e < E_EDGES) {
        int d = dst[e];
        int pos = atomicAdd(&g_cursor[d], 1);
        g_csr[pos] = make_int2(src[e], __float_as_int(w1[e]));
    }
}

// ---------------- GEMM1: 64x128, K-chunk 64, 3 CTAs/SM, fused proj epilogue ----
__device__ __forceinline__ void store_A_stage(__half* st, const float4* av, int tid) {
#pragma unroll
    for (int j = 0; j < 4; j++) {
        int idx = tid + (j << 8);          // 0..1023
        int r   = idx >> 4;                // 0..63
        int c4  = (idx & 15) << 2;         // 0..60
        float4 v = av[j];
        __half h0 = __float2half_rn(v.x);
        __half h1 = __float2half_rn(v.y);
        __half h2 = __float2half_rn(v.z);
        __half h3 = __float2half_rn(v.w);
        uint32_t hp0 = ((uint32_t)*(uint16_t*)&h1 << 16) | *(uint16_t*)&h0;
        uint32_t hp1 = ((uint32_t)*(uint16_t*)&h3 << 16) | *(uint16_t*)&h2;
        *(uint2*)&st[r * ASTR + c4] = make_uint2(hp0, hp1);
    }
}

__global__ __launch_bounds__(256, 3)
void k_gemm1_mma(const float* __restrict__ feat,
                 const float* __restrict__ Wm2, const float* __restrict__ Ws2) {
    extern __shared__ __half sm[];
    __shared__ float wm2s[H_DIM * C_DIM];
    __shared__ float ws2s[H_DIM * C_DIM];
    const int tid  = threadIdx.x;
    const int lane = tid & 31;
    const int wid  = tid >> 5;
    const int wm   = wid & 1;          // 2 row-warps (32 rows each)
    const int wn   = wid >> 1;         // 4 col-warps (32 interleaved cols each)
    const int rowbase = blockIdx.x * 64;
    const int h       = blockIdx.y;    // column half: interleaved cols h*128..+127
    const int la      = lane & 3;

    for (int i = tid; i < H_DIM * C_DIM; i += 256) {
        wm2s[i] = Wm2[i];
        ws2s[i] = Ws2[i];
    }

    const int a_lrow = (lane & 7) + ((lane >> 3) & 1) * 8;
    const int a_koff = (lane >> 4) * 16;
    const int b_lrow = (lane & 7);
    const int b_nsel = (lane >> 4);
    const int b_koff = ((lane >> 3) & 1) * 16;

    float acc[2][4][4];
#pragma unroll
    for (int mi = 0; mi < 2; mi++)
#pragma unroll
        for (int ni = 0; ni < 4; ni++)
#pragma unroll
            for (int q = 0; q < 4; q++) acc[mi][ni][q] = 0.f;

    float4 av[4];
    // ---- prologue: chunk 0 ----
#pragma unroll
    for (int j = 0; j < 4; j++) {
        int idx = tid + (j << 8);
        int r   = idx >> 4;
        int c4  = (idx & 15) << 2;
        int grow = rowbase + r;
        if (grow >= N_NODES) grow = N_NODES - 1;
        av[j] = *(const float4*)&feat[(size_t)grow * F_DIM + c4];
    }
#pragma unroll
    for (int j = 0; j < 4; j++) {
        int idx = tid + (j << 8);          // 0..1023
        int n   = idx >> 3;                // 0..127
        int seg = idx & 7;                 // 0..7
        uint32_t d = smem_u32(&sm[A_ELEMS + n * ASTR + seg * 8]);
        CP_ASYNC16(d, &g_Bt[(size_t)(h * 128 + n) * 512 + seg * 8]);
    }
    CP_COMMIT();
    store_A_stage(sm, av, tid);
    CP_WAIT0();
    __syncthreads();

#pragma unroll 1
    for (int chunk = 0; chunk < 8; chunk++) {
        __half* st  = sm + (chunk & 1) * STAGE;
        __half* stn = sm + ((chunk & 1) ^ 1) * STAGE;

        if (chunk < 7) {
            const int k0 = (chunk + 1) << 6;
#pragma unroll
            for (int j = 0; j < 4; j++) {
                int idx = tid + (j << 8);
                int r   = idx >> 4;
                int c4  = (idx & 15) << 2;
                int grow = rowbase + r;
                if (grow >= N_NODES) grow = N_NODES - 1;
                av[j] = *(const float4*)&feat[(size_t)grow * F_DIM + k0 + c4];
            }
#pragma unroll
            for (int j = 0; j < 4; j++) {
                int idx = tid + (j << 8);
                int n   = idx >> 3;
                int seg = idx & 7;
                uint32_t d = smem_u32(&stn[A_ELEMS + n * ASTR + seg * 8]);
                CP_ASYNC16(d, &g_Bt[(size_t)(h * 128 + n) * 512 + k0 + seg * 8]);
            }
            CP_COMMIT();
        }

        const uint32_t sA = smem_u32(st);
        const uint32_t sB = sA + A_ELEMS * 2;
#pragma unroll
        for (int ks = 0; ks < 4; ks++) {
            const uint32_t kbyte = ks * 32;
            uint32_t ahf[2][4];
#pragma unroll
            for (int mi = 0; mi < 2; mi++) {
                uint32_t ro = (uint32_t)(wm * 32 + mi * 16 + a_lrow) * (ASTR * 2) + kbyte + a_koff;
                LDSM4(ahf[mi][0], ahf[mi][1], ahf[mi][2], ahf[mi][3], sA + ro);
            }
#pragma unroll
            for (int nip = 0; nip < 2; nip++) {
                uint32_t bo = (uint32_t)(wn * 32 + (nip * 2 + b_nsel) * 8 + b_lrow) * (ASTR * 2)
                              + kbyte + b_koff;
                uint32_t b0, b1, b2, b3;
                LDSM4(b0, b1, b2, b3, sB + bo);
#pragma unroll
                for (int mi = 0; mi < 2; mi++) {
                    MMA16816(acc[mi][2 * nip],     ahf[mi], b0, b1);
                    MMA16816(acc[mi][2 * nip + 1], ahf[mi], b2, b3);
                }
            }
        }

        if (chunk < 7) {
            store_A_stage(stn, av, tid);
            CP_WAIT0();
        }
        __syncthreads();
    }

    // ---- epilogue: activations + fused 128->8 projection + atomic reduce ----
    const int chbase = h * 64 + wn * 16;
#pragma unroll
    for (int mi = 0; mi < 2; mi++) {
#pragma unroll
        for (int half8 = 0; half8 < 2; half8++) {
            int row = rowbase + wm * 32 + mi * 16 + half8 * 8 + (lane >> 2);
            float pa[8], pb[8];
#pragma unroll
            for (int c = 0; c < 8; c++) { pa[c] = 0.f; pb[c] = 0.f; }
#pragma unroll
            for (int ni = 0; ni < 4; ni++) {
                float m  = acc[mi][ni][half8 * 2 + 0];
                float s  = acc[mi][ni][half8 * 2 + 1];
                float sr = fmaxf(s, 0.f);
                float a1 = __expf(-sr);
                float e  = (m > 0.f) ? m : expm1f(m);
                float xa = e * a1;
                float xb = sr * a1 * a1;
                int ch = chbase + ni * 4 + la;
#pragma unroll
                for (int c = 0; c < 8; c++) {
                    pa[c] = fmaf(xa, wm2s[ch * 8 + c], pa[c]);
                    pb[c] = fmaf(xb, ws2s[ch * 8 + c], pb[c]);
                }
            }
#pragma unroll
            for (int o = 1; o <= 2; o <<= 1) {
#pragma unroll
                for (int c = 0; c < 8; c++) {
                    pa[c] += __shfl_xor_sync(0xffffffffu, pa[c], o);
                    pb[c] += __shfl_xor_sync(0xffffffffu, pb[c], o);
                }
            }
            if (row < N_NODES) {
                int c0 = la * 2;
                atomicAdd(&g_pa[(size_t)row * C_DIM + c0],     pa[c0]);
                atomicAdd(&g_pa[(size_t)row * C_DIM + c0 + 1], pa[c0 + 1]);
                atomicAdd(&g_pb[(size_t)row * C_DIM + c0],     pb[c0]);
                atomicAdd(&g_pb[(size_t)row * C_DIM + c0 + 1], pb[c0 + 1]);
            }
        }
    }
}

// ---------------- agg in 8-dim + layer-2 activations ----------------
__global__ __launch_bounds__(256)
void k_agg1p() {
    int n    = (blockIdx.x * blockDim.x + threadIdx.x) >> 5;
    int lane = threadIdx.x & 31;
    if (n >= N_NODES) return;
    int s = g_rowstart[n];
    int e = g_rowstart[n + 1];
    int c = lane & 7;
    int g = lane >> 3;
    float a1 = 0.f, a2 = 0.f;
    for (int j = s + g; j < e; j += 4) {
        int2 e2 = g_csr[j];
        float w1 = __int_as_float(e2.y);
        float w2 = w1 * w1;
        a1 = fmaf(w1, g_pa[(size_t)e2.x * C_DIM + c], a1);
        a2 = fmaf(w2, g_pb[(size_t)e2.x * C_DIM + c], a2);
    }
    a1 += __shfl_down_sync(0xffffffffu, a1, 16);
    a2 += __shfl_down_sync(0xffffffffu, a2, 16);
    a1 += __shfl_down_sync(0xffffffffu, a1, 8);
    a2 += __shfl_down_sync(0xffffffffu, a2, 8);
    if (lane < 8) {
        float s2   = fmaxf(a2, 0.f);
        float miu2 = (a1 > 0.f) ? a1 : expm1f(a1);
        g_ma[(size_t)n * C_DIM + lane] = miu2 * __expf(-s2);
        g_s2[(size_t)n * C_DIM + lane] = s2;
    }
}

// ---------------- Aggregation 2 + reparameterized sample ----------------
__global__ __launch_bounds__(256)
void k_agg2(const float* __restrict__ noise, float* __restrict__ out) {
    int n    = (blockIdx.x * blockDim.x + threadIdx.x) >> 5;
    int lane = threadIdx.x & 31;
    if (n >= N_NODES) return;
    int s = g_rowstart[n];
    int e = g_rowstart[n + 1];
    int c = lane & 7;
    int g = lane >> 3;
    float acc = 0.f;
    for (int j = s + g; j < e; j += 4) {
        int2 e2 = g_csr[j];
        float w = __int_as_float(e2.y);
        acc = fmaf(w, g_ma[(size_t)e2.x * C_DIM + c], acc);
    }
    acc += __shfl_down_sync(0xffffffffu, acc, 16);
    acc += __shfl_down_sync(0xffffffffu, acc, 8);
    if (lane < 8) {
        size_t o = (size_t)n * C_DIM + c;
        float s2 = g_s2[o];
        out[o] = acc + noise[o] * sqrtf(s2 + EPSV);
    }
}

// ---------------- launch: fork CSR chain onto a side stream under the GEMM ----
extern "C" void kernel_launch(void* const* d_in, const int* in_sizes, int n_in,
                              void* d_out, int out_size) {
    (void)in_sizes; (void)n_in; (void)out_size;
    const float* feat  = (const float*)d_in[0];
    const int*   esrc  = (const int*)d_in[1];
    const int*   edst  = (const int*)d_in[2];
    const float* w1    = (const float*)d_in[3];
    const float* Wm1   = (const float*)d_in[5];
    const float* Ws1   = (const float*)d_in[6];
    const float* Wm2   = (const float*)d_in[7];
    const float* Ws2   = (const float*)d_in[8];
    const float* noise = (const float*)d_in[9];
    float*       out   = (float*)d_out;

    static cudaStream_t s2 = nullptr;
    static cudaEvent_t  evF = nullptr, evJ = nullptr;
    static bool         inited = false;
    if (!inited) {
        cudaFuncSetAttribute(k_gemm1_mma, cudaFuncAttributeMaxDynamicSharedMemorySize,
                             SMEM_GEMM);
        cudaStreamCreateWithFlags(&s2, cudaStreamNonBlocking);
        cudaEventCreateWithFlags(&evF, cudaEventDisableTiming);
        cudaEventCreateWithFlags(&evJ, cudaEventDisableTiming);
        inited = true;
    }

    // main: prep (zeros deg/pa/pb + Bt) -- both chains depend on it
    k_prep<<<(N_NODES * C_DIM + CH - 1) / CH, CH>>>(Wm1, Ws1);

    // fork
    cudaEventRecord(evF, 0);
    cudaStreamWaitEvent(s2, evF, 0);

    // side stream: CSR build chain (independent of GEMM)
    k_hist<<<(E_EDGES + 255) / 256, 256, 0, s2>>>(edst);
    k_blocksum<<<NB, CH, 0, s2>>>();
    k_offscan<<<1, 128, 0, s2>>>();
    k_scan_chunk<<<NB, CH, 0, s2>>>();
    k_scatter<<<(E_EDGES + 255) / 256, 256, 0, s2>>>(esrc, edst, w1);

    // main: the big GEMM (hides the CSR chain)
    dim3 g1((N_NODES + 63) / 64, 2);
    k_gemm1_mma<<<g1, 256, SMEM_GEMM>>>(feat, Wm2, Ws2);

    // join
    cudaEventRecord(evJ, s2);
    cudaStreamWaitEvent(0, evJ, 0);

    // main: aggregations (need both CSR and GEMM results)
    k_agg1p<<<(N_NODES + 7) / 8, 256>>>();
    k_agg2<<<(N_NODES + 7) / 8, 256>>>(noise, out);
}